// round 1
// baseline (speedup 1.0000x reference)
#include <cuda_runtime.h>

// Problem constants
#define BB 2
#define NN 512
#define HH 128
#define DD 128
#define TT 8
#define ZZ 256

#define RET_ELEMS (BB*NN*DD)          // 131072

// Scratch (device globals; no allocation allowed)
__device__ float g_A1[BB*NN*DD];      // m1 + mg + biases (depends on j)
__device__ float g_M2[BB*NN*DD];      // m2 + bias        (depends on i)
__device__ float g_O1[BB*NN*DD];      // z@Wo1 + bo1 + bo2
__device__ float g_TTJ[BB*NN*TT];     // t1 + tg + bt1 + bte + btg (depends on j)
__device__ float g_TTI[BB*NN*TT];     // t2 + bt2                  (depends on i)
__device__ float g_MSGS[BB*NN*DD];    // max-reduced messages

// ---------------------------------------------------------------------------
// Kernel 1: per-node linear layers (small GEMMs), bias folding.
// grid = 128 blocks, each handles 8 consecutive rows (row = b*N + n).
// ---------------------------------------------------------------------------
__global__ __launch_bounds__(128) void setup_kernel(
    const float* __restrict__ node, const float* __restrict__ hidden,
    const float* __restrict__ graph,
    const float* __restrict__ Wm1, const float* __restrict__ bm1,
    const float* __restrict__ Wm2, const float* __restrict__ bm2,
    const float* __restrict__ bme,
    const float* __restrict__ Wmg, const float* __restrict__ bmg,
    const float* __restrict__ Wo1, const float* __restrict__ bo1,
    const float* __restrict__ bo2,
    const float* __restrict__ Wt1, const float* __restrict__ bt1,
    const float* __restrict__ Wt2, const float* __restrict__ bt2,
    const float* __restrict__ bte,
    const float* __restrict__ Wtg, const float* __restrict__ btg)
{
    __shared__ float Zs[8 * ZZ];   // 8 rows x 256
    __shared__ float Gs[HH];

    const int tid  = threadIdx.x;
    const int row0 = blockIdx.x * 8;        // 8 | N so all rows share b
    const int b    = row0 / NN;

    // load z = concat(node, hidden) for 8 rows
    #pragma unroll
    for (int s = 0; s < 16; s++) {
        int idx = tid + 128 * s;            // 0..2047
        int r = idx >> 8, k = idx & 255;
        Zs[idx] = (k < HH) ? node[(row0 + r) * HH + k]
                           : hidden[(row0 + r) * HH + (k - HH)];
    }
    if (tid < HH) Gs[tid] = graph[b * HH + tid];
    __syncthreads();

    const int d = tid;  // output channel 0..127

    // graph message channel d
    float mgd = bmg[d];
    #pragma unroll 8
    for (int k = 0; k < HH; k++) mgd += Gs[k] * Wmg[k * DD + d];

    float a1[8], a2[8], ao[8];
    #pragma unroll
    for (int r = 0; r < 8; r++) { a1[r] = 0.f; a2[r] = 0.f; ao[r] = 0.f; }

    #pragma unroll 4
    for (int k = 0; k < ZZ; k++) {
        float w1 = Wm1[k * DD + d];
        float w2 = Wm2[k * DD + d];
        float wo = Wo1[k * DD + d];
        #pragma unroll
        for (int r = 0; r < 8; r++) {
            float zv = Zs[r * ZZ + k];
            a1[r] += zv * w1; a2[r] += zv * w2; ao[r] += zv * wo;
        }
    }
    const float c1 = bm1[d] + mgd + bme[d];
    const float c2 = bm2[d];
    const float co = bo1[d] + bo2[d];
    #pragma unroll
    for (int r = 0; r < 8; r++) {
        g_A1[(row0 + r) * DD + d] = a1[r] + c1;
        g_M2[(row0 + r) * DD + d] = a2[r] + c2;
        g_O1[(row0 + r) * DD + d] = ao[r] + co;
    }

    // triplet per-node parts: tid -> (r = tid/16, tt = tid%16)
    {
        int r  = tid >> 4;
        int tt = tid & 15;
        if (tt < TT) {
            int t = tt;
            float tg = btg[t];
            for (int k = 0; k < HH; k++) tg += Gs[k] * Wtg[k * TT + t];
            float s = bt1[t] + bte[t] + tg;
            for (int k = 0; k < ZZ; k++) s += Zs[r * ZZ + k] * Wt1[k * TT + t];
            g_TTJ[(row0 + r) * TT + t] = s;
        } else {
            int t = tt - TT;
            float s = bt2[t];
            for (int k = 0; k < ZZ; k++) s += Zs[r * ZZ + k] * Wt2[k * TT + t];
            g_TTI[(row0 + r) * TT + t] = s;
        }
    }
}

// ---------------------------------------------------------------------------
// Kernel 2: fused edge GEMM + masked max + triplet GEMM + relu.
// One block per (b, j). 256 threads = 8 row-groups (tr) x 32 col-groups (tc).
// Each thread: 8 rows x 4 cols register tile of msg_e for the current
// 64-row sender chunk; running max in registers across chunks.
// ---------------------------------------------------------------------------
#define TI    64
#define EPAD  132              // 64x132 padded SMEM tile (bank-conflict-free)

// dynamic smem layout (floats)
#define OFF_WS   0                         // Wme  128x128
#define OFF_WT   (OFF_WS + DD*DD)          // Wte  128x8
#define OFF_ES   (OFF_WT + HH*TT)          // edge chunk 64x132
#define OFF_ADJ  (OFF_ES + TI*EPAD)        // adj chunk 64
#define OFF_TTJ  (OFF_ADJ + TI)            // ttj 8
#define SMEM_FLOATS (OFF_TTJ + TT)
#define SMEM_BYTES  (SMEM_FLOATS * 4)      // 103,712 B -> 2 blocks/SM

__global__ __launch_bounds__(256, 2) void main_kernel(
    const float* __restrict__ edge, const float* __restrict__ adj,
    const float* __restrict__ Wme,  const float* __restrict__ Wte,
    float* __restrict__ out)
{
    extern __shared__ float smem[];
    float* Ws   = smem + OFF_WS;
    float* Wt   = smem + OFF_WT;
    float* Es   = smem + OFF_ES;
    float* adjs = smem + OFF_ADJ;
    float* ttjs = smem + OFF_TTJ;

    const int tid = threadIdx.x;
    const int tc  = tid & 31;      // col group (4 cols)
    const int tr  = tid >> 5;      // row group (8 rows) == warp id
    const int bj  = blockIdx.x;    // b*N + j
    const int b   = bj >> 9;
    const int j   = bj & 511;

    // stage weights
    {
        const float4* w4 = (const float4*)Wme;
        float4* s4 = (float4*)Ws;
        #pragma unroll
        for (int s = 0; s < 16; s++) s4[tid + 256 * s] = w4[tid + 256 * s];
        ((float4*)Wt)[tid] = ((const float4*)Wte)[tid];   // 256 float4 = 1024 floats
        if (tid < TT) ttjs[tid] = g_TTJ[bj * TT + tid];
    }

    float a1c[4];
    {
        float4 v = *(const float4*)&g_A1[bj * DD + tc * 4];
        a1c[0] = v.x; a1c[1] = v.y; a1c[2] = v.z; a1c[3] = v.w;
    }

    float cmax[4];
    #pragma unroll
    for (int c = 0; c < 4; c++) cmax[c] = -3.402823466e38f;

    for (int chunk = 0; chunk < NN / TI; chunk++) {
        const int i0 = chunk * TI;
        __syncthreads();   // protect Es/adjs from previous iteration readers

        // cooperative load: 64 rows x 128 floats of edge_fts[b, i0+., j, :]
        #pragma unroll
        for (int s = 0; s < 8; s++) {
            int f4   = tid + 256 * s;      // 0..2047
            int rrow = f4 >> 5;
            int kk   = f4 & 31;
            float4 v = *(const float4*)&edge[((b * NN + i0 + rrow) * NN + j) * HH + kk * 4];
            *(float4*)&Es[rrow * EPAD + kk * 4] = v;
        }
        if (tid < TI) adjs[tid] = adj[(b * NN + i0 + tid) * NN + j];
        __syncthreads();

        // 64x128 GEMM vs SMEM Wme, register tile 8x4
        float acc[8][4];
        #pragma unroll
        for (int rr = 0; rr < 8; rr++)
            #pragma unroll
            for (int c = 0; c < 4; c++) acc[rr][c] = 0.f;

        #pragma unroll 4
        for (int k = 0; k < HH; k++) {
            float4 w = *(float4*)&Ws[k * DD + tc * 4];
            #pragma unroll
            for (int rr = 0; rr < 8; rr++) {
                float e = Es[(tr * 8 + rr) * EPAD + k];   // broadcast within warp
                acc[rr][0] += e * w.x;
                acc[rr][1] += e * w.y;
                acc[rr][2] += e * w.z;
                acc[rr][3] += e * w.w;
            }
        }

        // epilogue: + a1 + m2[i], mask, running max
        #pragma unroll
        for (int rr = 0; rr < 8; rr++) {
            int i = i0 + tr * 8 + rr;
            float a = adjs[tr * 8 + rr];
            float4 m2v = *(const float4*)&g_M2[(b * NN + i) * DD + tc * 4];
            float v0 = a * (acc[rr][0] + a1c[0] + m2v.x);
            float v1 = a * (acc[rr][1] + a1c[1] + m2v.y);
            float v2 = a * (acc[rr][2] + a1c[2] + m2v.z);
            float v3 = a * (acc[rr][3] + a1c[3] + m2v.w);
            cmax[0] = fmaxf(cmax[0], v0);
            cmax[1] = fmaxf(cmax[1], v1);
            cmax[2] = fmaxf(cmax[2], v2);
            cmax[3] = fmaxf(cmax[3], v3);
        }

        // triplet GEMM (N=8) from same chunk: thread -> (row = tid/4, 2 t's)
        {
            int rowq = tid >> 2;
            int t0   = (tid & 3) * 2;
            float s0 = 0.f, s1 = 0.f;
            #pragma unroll 8
            for (int k = 0; k < HH; k++) {
                float e = Es[rowq * EPAD + k];
                s0 += e * Wt[k * TT + t0];
                s1 += e * Wt[k * TT + t0 + 1];
            }
            int i = i0 + rowq;
            float2 ti2 = *(const float2*)&g_TTI[(b * NN + i) * TT + t0];
            float r0 = fmaxf(s0 + ti2.x + ttjs[t0], 0.f);
            float r1 = fmaxf(s1 + ti2.y + ttjs[t0 + 1], 0.f);
            float2 o; o.x = r0; o.y = r1;
            *(float2*)&out[RET_ELEMS + (size_t)((b * NN + i) * NN + j) * TT + t0] = o;
        }
    }

    // cross-warp max reduction (reuse Es)
    __syncthreads();
    #pragma unroll
    for (int c = 0; c < 4; c++) Es[tr * EPAD + tc * 4 + c] = cmax[c];
    __syncthreads();
    if (tid < DD) {
        float m = Es[tid];
        #pragma unroll
        for (int g = 1; g < 8; g++) m = fmaxf(m, Es[g * EPAD + tid]);
        g_MSGS[bj * DD + tid] = m;
    }
}

// ---------------------------------------------------------------------------
// Kernel 3: ret = o1 + msgs @ Wo2  (bo1, bo2 already folded into g_O1)
// ---------------------------------------------------------------------------
__global__ __launch_bounds__(128) void ret_kernel(
    const float* __restrict__ Wo2, float* __restrict__ out)
{
    __shared__ float ms[DD];
    const int bj = blockIdx.x;
    const int d  = threadIdx.x;
    ms[d] = g_MSGS[bj * DD + d];
    __syncthreads();
    float acc = g_O1[bj * DD + d];
    #pragma unroll 8
    for (int k = 0; k < DD; k++) acc += ms[k] * Wo2[k * DD + d];
    out[bj * DD + d] = acc;
}

// ---------------------------------------------------------------------------
extern "C" void kernel_launch(void* const* d_in, const int* in_sizes, int n_in,
                              void* d_out, int out_size)
{
    const float* node   = (const float*)d_in[0];
    const float* edge   = (const float*)d_in[1];
    const float* graph  = (const float*)d_in[2];
    const float* adj    = (const float*)d_in[3];
    const float* hidden = (const float*)d_in[4];
    const float* Wm1 = (const float*)d_in[5];  const float* bm1 = (const float*)d_in[6];
    const float* Wm2 = (const float*)d_in[7];  const float* bm2 = (const float*)d_in[8];
    const float* Wme = (const float*)d_in[9];  const float* bme = (const float*)d_in[10];
    const float* Wmg = (const float*)d_in[11]; const float* bmg = (const float*)d_in[12];
    const float* Wo1 = (const float*)d_in[13]; const float* bo1 = (const float*)d_in[14];
    const float* Wo2 = (const float*)d_in[15]; const float* bo2 = (const float*)d_in[16];
    const float* Wt1 = (const float*)d_in[17]; const float* bt1 = (const float*)d_in[18];
    const float* Wt2 = (const float*)d_in[19]; const float* bt2 = (const float*)d_in[20];
    const float* Wte = (const float*)d_in[21]; const float* bte = (const float*)d_in[22];
    const float* Wtg = (const float*)d_in[23]; const float* btg = (const float*)d_in[24];

    float* out = (float*)d_out;

    cudaFuncSetAttribute(main_kernel, cudaFuncAttributeMaxDynamicSharedMemorySize,
                         SMEM_BYTES);

    setup_kernel<<<128, 128>>>(node, hidden, graph,
                               Wm1, bm1, Wm2, bm2, bme, Wmg, bmg,
                               Wo1, bo1, bo2,
                               Wt1, bt1, Wt2, bt2, bte, Wtg, btg);

    main_kernel<<<BB * NN, 256, SMEM_BYTES>>>(edge, adj, Wme, Wte, out);

    ret_kernel<<<BB * NN, 128>>>(Wo2, out);
}

// round 2
// speedup vs baseline: 1.0976x; 1.0976x over previous
#include <cuda_runtime.h>

// Problem constants
#define BB 2
#define NN 512
#define HH 128
#define DD 128
#define TT 8
#define ZZ 256

#define TI    128              // sender rows per chunk
#define EPAD  132              // padded row stride for Es (bank-conflict-free)
#define RET_ELEMS (BB*NN*DD)

// Scratch (device globals; no allocation allowed)
__device__ float g_A1[BB*NN*DD];      // m1 + mg + bm1 + bme          (by j)
__device__ float g_M2[BB*NN*DD];      // m2 + bm2                     (by i)
__device__ float g_O1[BB*NN*DD];      // z@Wo1 + bo1 + bo2            (by j)
__device__ float g_TTJ[BB*NN*TT];     // t1 + tg + bt1 + bte + btg    (by j)
__device__ float g_TTI[BB*NN*TT];     // t2 + bt2                     (by i)

// packed f32x2 helpers
#define FMA2(acc, a, b) asm("fma.rn.f32x2 %0, %1, %2, %0;" : "+l"(acc) : "l"(a), "l"(b))
#define DUP2(d, s)      asm("mov.b64 %0, {%1, %1};" : "=l"(d) : "f"(s))
#define UNPK(lo, hi, s) asm("mov.b64 {%0, %1}, %2;" : "=f"(lo), "=f"(hi) : "l"(s))

__device__ __forceinline__ void cp16(float* dst, const float* src) {
    unsigned s = (unsigned)__cvta_generic_to_shared(dst);
    asm volatile("cp.async.cg.shared.global [%0], [%1], 16;" :: "r"(s), "l"(src));
}
__device__ __forceinline__ void cp4(float* dst, const float* src) {
    unsigned s = (unsigned)__cvta_generic_to_shared(dst);
    asm volatile("cp.async.ca.shared.global [%0], [%1], 4;" :: "r"(s), "l"(src));
}
#define CP_COMMIT() asm volatile("cp.async.commit_group;" ::: "memory")

// ---------------------------------------------------------------------------
// Kernel 1: per-node linears. grid = (128 row-groups, 4); y in {0,1,2} does
// one Z x D matrix for 8 rows; y==3 does the triplet (T=8) linears.
// ---------------------------------------------------------------------------
__global__ __launch_bounds__(128) void setup_kernel(
    const float* __restrict__ node, const float* __restrict__ hidden,
    const float* __restrict__ graph,
    const float* __restrict__ Wm1, const float* __restrict__ bm1,
    const float* __restrict__ Wm2, const float* __restrict__ bm2,
    const float* __restrict__ bme,
    const float* __restrict__ Wmg, const float* __restrict__ bmg,
    const float* __restrict__ Wo1, const float* __restrict__ bo1,
    const float* __restrict__ bo2,
    const float* __restrict__ Wt1, const float* __restrict__ bt1,
    const float* __restrict__ Wt2, const float* __restrict__ bt2,
    const float* __restrict__ bte,
    const float* __restrict__ Wtg, const float* __restrict__ btg)
{
    __shared__ float Zs[8 * ZZ];
    __shared__ float Gs[HH];

    const int tid  = threadIdx.x;
    const int row0 = blockIdx.x * 8;
    const int b    = row0 / NN;
    const int m    = blockIdx.y;

    #pragma unroll
    for (int s = 0; s < 16; s++) {
        int idx = tid + 128 * s;
        int r = idx >> 8, k = idx & 255;
        Zs[idx] = (k < HH) ? node[(row0 + r) * HH + k]
                           : hidden[(row0 + r) * HH + (k - HH)];
    }
    if (tid < HH) Gs[tid] = graph[b * HH + tid];
    __syncthreads();

    if (m < 3) {
        const float* W = (m == 0) ? Wm1 : (m == 1) ? Wm2 : Wo1;
        const int d = tid;
        float acc[8];
        #pragma unroll
        for (int r = 0; r < 8; r++) acc[r] = 0.f;

        #pragma unroll 8
        for (int k = 0; k < ZZ; k++) {
            float w = W[k * DD + d];
            #pragma unroll
            for (int r = 0; r < 8; r++) acc[r] += Zs[r * ZZ + k] * w;
        }

        float cst;
        float* dst;
        if (m == 0) {
            float mgd = bmg[d];
            #pragma unroll 8
            for (int k = 0; k < HH; k++) mgd += Gs[k] * Wmg[k * DD + d];
            cst = bm1[d] + bme[d] + mgd;
            dst = g_A1;
        } else if (m == 1) {
            cst = bm2[d];
            dst = g_M2;
        } else {
            cst = bo1[d] + bo2[d];
            dst = g_O1;
        }
        #pragma unroll
        for (int r = 0; r < 8; r++) dst[(row0 + r) * DD + d] = acc[r] + cst;
    } else {
        int r  = tid >> 4;
        int tt = tid & 15;
        if (tt < TT) {
            int t = tt;
            float tg = btg[t];
            for (int k = 0; k < HH; k++) tg += Gs[k] * Wtg[k * TT + t];
            float s = bt1[t] + bte[t] + tg;
            for (int k = 0; k < ZZ; k++) s += Zs[r * ZZ + k] * Wt1[k * TT + t];
            g_TTJ[(row0 + r) * TT + t] = s;
        } else {
            int t = tt - TT;
            float s = bt2[t];
            for (int k = 0; k < ZZ; k++) s += Zs[r * ZZ + k] * Wt2[k * TT + t];
            g_TTI[(row0 + r) * TT + t] = s;
        }
    }
}

// ---------------------------------------------------------------------------
// Kernel 2: fused edge GEMM (f32x2) + masked max + triplet GEMM + relu + ret.
// One block per (b, j). 256 threads: tc = tid%16 -> cols {tc*4..+3, 64+tc*4..+3},
// tr = tid/16 -> rows {rr*16 + tr}. Double-buffered cp.async chunk staging.
// ---------------------------------------------------------------------------
// dynamic smem layout (floats)
#define OFF_WS   0                         // Wme 128x128
#define OFF_WT   (OFF_WS + DD*DD)          // Wte 128x8
#define OFF_ES   (OFF_WT + HH*TT)          // 2 x (128 x 132)
#define OFF_ADJ  (OFF_ES + 2*TI*EPAD)      // 2 x 128
#define OFF_TTJ  (OFF_ADJ + 2*TI)          // 8
#define SMEM_FLOATS (OFF_TTJ + TT)
#define SMEM_BYTES  (SMEM_FLOATS * 4)      // 205,856 B -> 1 block/SM

__global__ __launch_bounds__(256) void main_kernel(
    const float* __restrict__ edge, const float* __restrict__ adj,
    const float* __restrict__ Wme,  const float* __restrict__ Wte,
    const float* __restrict__ Wo2,  float* __restrict__ out)
{
    extern __shared__ float smem[];
    float* Ws   = smem + OFF_WS;
    float* Wt   = smem + OFF_WT;
    float* Es   = smem + OFF_ES;
    float* adjs = smem + OFF_ADJ;
    float* ttjs = smem + OFF_TTJ;

    const int tid = threadIdx.x;
    const int tc  = tid & 15;
    const int tr  = tid >> 4;
    const int bj  = blockIdx.x;
    const int b   = bj >> 9;
    const int j   = bj & 511;
    const int c0  = tc * 4;
    const int c1  = 64 + tc * 4;

    // stage weights (group 0)
    {
        const float4* wsrc = (const float4*)Wme;
        #pragma unroll
        for (int s = 0; s < 16; s++)
            cp16((float*)&((float4*)Ws)[tid + 256 * s], (const float*)&wsrc[tid + 256 * s]);
        cp16((float*)&((float4*)Wt)[tid], (const float*)&((const float4*)Wte)[tid]);
    }
    CP_COMMIT();

    auto stage = [&](int chunk, int buf) {
        const int i0 = chunk * TI;
        float* Eb = Es + buf * (TI * EPAD);
        #pragma unroll
        for (int s = 0; s < 16; s++) {
            int f4  = tid + 256 * s;           // 0..4095
            int row = f4 >> 5;
            int kk  = f4 & 31;
            cp16(&Eb[row * EPAD + kk * 4],
                 &edge[((b * NN + i0 + row) * NN + j) * HH + kk * 4]);
        }
        if (tid < TI) cp4(&adjs[buf * TI + tid], &adj[(b * NN + i0 + tid) * NN + j]);
        CP_COMMIT();
    };

    stage(0, 0);

    if (tid < TT) ttjs[tid] = g_TTJ[bj * TT + tid];
    float4 a1A = *(const float4*)&g_A1[bj * DD + c0];
    float4 a1B = *(const float4*)&g_A1[bj * DD + c1];

    float cmax[8];
    #pragma unroll
    for (int q = 0; q < 8; q++) cmax[q] = -3.402823466e38f;

    for (int c = 0; c < NN / TI; c++) {
        const int buf = c & 1;
        const int i0  = c * TI;
        if (c < NN / TI - 1) {
            stage(c + 1, buf ^ 1);
            asm volatile("cp.async.wait_group 1;" ::: "memory");
        } else {
            asm volatile("cp.async.wait_group 0;" ::: "memory");
        }
        __syncthreads();

        const float* Eb = Es + buf * (TI * EPAD);

        // ---- 128x128 GEMM chunk, packed f32x2, tile 8 rows x 4 col-pairs ----
        unsigned long long acc[8][4];
        #pragma unroll
        for (int rr = 0; rr < 8; rr++)
            #pragma unroll
            for (int q = 0; q < 4; q++) acc[rr][q] = 0ULL;

        #pragma unroll 4
        for (int k = 0; k < HH; k++) {
            ulonglong2 wA = *(const ulonglong2*)&Ws[k * DD + c0];
            ulonglong2 wB = *(const ulonglong2*)&Ws[k * DD + c1];
            #pragma unroll
            for (int rr = 0; rr < 8; rr++) {
                float e = Eb[(rr * 16 + tr) * EPAD + k];
                unsigned long long ep; DUP2(ep, e);
                FMA2(acc[rr][0], ep, wA.x);
                FMA2(acc[rr][1], ep, wA.y);
                FMA2(acc[rr][2], ep, wB.x);
                FMA2(acc[rr][3], ep, wB.y);
            }
        }

        // ---- epilogue: + a1 + m2[i], mask, running max ----
        #pragma unroll
        for (int rr = 0; rr < 8; rr++) {
            int r = rr * 16 + tr;
            int i = i0 + r;
            float a = adjs[buf * TI + r];
            const float* m2p = &g_M2[(b * NN + i) * DD];
            float4 mA = *(const float4*)&m2p[c0];
            float4 mB = *(const float4*)&m2p[c1];
            float f0, f1, f2, f3, f4v, f5, f6, f7;
            UNPK(f0, f1, acc[rr][0]);
            UNPK(f2, f3, acc[rr][1]);
            UNPK(f4v, f5, acc[rr][2]);
            UNPK(f6, f7, acc[rr][3]);
            cmax[0] = fmaxf(cmax[0], a * (f0 + a1A.x + mA.x));
            cmax[1] = fmaxf(cmax[1], a * (f1 + a1A.y + mA.y));
            cmax[2] = fmaxf(cmax[2], a * (f2 + a1A.z + mA.z));
            cmax[3] = fmaxf(cmax[3], a * (f3 + a1A.w + mA.w));
            cmax[4] = fmaxf(cmax[4], a * (f4v + a1B.x + mB.x));
            cmax[5] = fmaxf(cmax[5], a * (f5 + a1B.y + mB.y));
            cmax[6] = fmaxf(cmax[6], a * (f6 + a1B.z + mB.z));
            cmax[7] = fmaxf(cmax[7], a * (f7 + a1B.w + mB.w));
        }

        // ---- triplet GEMM (T=8), packed: 2 threads per row, interleaved k ----
        {
            const int row = tid >> 1;
            const int h   = tid & 1;
            unsigned long long t4[4] = {0ULL, 0ULL, 0ULL, 0ULL};
            #pragma unroll 4
            for (int kk = 0; kk < HH / 2; kk++) {
                int k = kk * 2 + h;
                float e = Eb[row * EPAD + k];
                unsigned long long ep; DUP2(ep, e);
                ulonglong2 w0 = *(const ulonglong2*)&Wt[k * TT];
                ulonglong2 w1 = *(const ulonglong2*)&Wt[k * TT + 4];
                FMA2(t4[0], ep, w0.x);
                FMA2(t4[1], ep, w0.y);
                FMA2(t4[2], ep, w1.x);
                FMA2(t4[3], ep, w1.y);
            }
            float s[8];
            UNPK(s[0], s[1], t4[0]);
            UNPK(s[2], s[3], t4[1]);
            UNPK(s[4], s[5], t4[2]);
            UNPK(s[6], s[7], t4[3]);
            #pragma unroll
            for (int q = 0; q < 8; q++)
                s[q] += __shfl_xor_sync(0xffffffffu, s[q], 1);
            if (h == 0) {
                int i = i0 + row;
                const float* tip = &g_TTI[(b * NN + i) * TT];
                float4 o0, o1;
                o0.x = fmaxf(s[0] + tip[0] + ttjs[0], 0.f);
                o0.y = fmaxf(s[1] + tip[1] + ttjs[1], 0.f);
                o0.z = fmaxf(s[2] + tip[2] + ttjs[2], 0.f);
                o0.w = fmaxf(s[3] + tip[3] + ttjs[3], 0.f);
                o1.x = fmaxf(s[4] + tip[4] + ttjs[4], 0.f);
                o1.y = fmaxf(s[5] + tip[5] + ttjs[5], 0.f);
                o1.z = fmaxf(s[6] + tip[6] + ttjs[6], 0.f);
                o1.w = fmaxf(s[7] + tip[7] + ttjs[7], 0.f);
                float* op = &out[RET_ELEMS + (size_t)((b * NN + i) * NN + j) * TT];
                *(float4*)op = o0;
                *(float4*)(op + 4) = o1;
            }
        }
        __syncthreads();
    }

    // ---- cross-thread max reduction over the 16 tr groups ----
    float* red = Es;                       // safe: all staging complete
    red[tr * EPAD + c0 + 0] = cmax[0];
    red[tr * EPAD + c0 + 1] = cmax[1];
    red[tr * EPAD + c0 + 2] = cmax[2];
    red[tr * EPAD + c0 + 3] = cmax[3];
    red[tr * EPAD + c1 + 0] = cmax[4];
    red[tr * EPAD + c1 + 1] = cmax[5];
    red[tr * EPAD + c1 + 2] = cmax[6];
    red[tr * EPAD + c1 + 3] = cmax[7];
    __syncthreads();

    float* ms = Wt;                        // reuse: Wt no longer needed
    if (tid < DD) {
        float m = red[tid];
        #pragma unroll
        for (int g = 1; g < 16; g++) m = fmaxf(m, red[g * EPAD + tid]);
        ms[tid] = m;
    }
    __syncthreads();

    // ---- fused ret: out[bj] = o1 + msgs @ Wo2 ----
    if (tid < DD) {
        float acc = g_O1[bj * DD + tid];
        #pragma unroll 8
        for (int k = 0; k < DD; k++) acc += ms[k] * Wo2[k * DD + tid];
        out[bj * DD + tid] = acc;
    }
}

// ---------------------------------------------------------------------------
extern "C" void kernel_launch(void* const* d_in, const int* in_sizes, int n_in,
                              void* d_out, int out_size)
{
    const float* node   = (const float*)d_in[0];
    const float* edge   = (const float*)d_in[1];
    const float* graph  = (const float*)d_in[2];
    const float* adj    = (const float*)d_in[3];
    const float* hidden = (const float*)d_in[4];
    const float* Wm1 = (const float*)d_in[5];  const float* bm1 = (const float*)d_in[6];
    const float* Wm2 = (const float*)d_in[7];  const float* bm2 = (const float*)d_in[8];
    const float* Wme = (const float*)d_in[9];  const float* bme = (const float*)d_in[10];
    const float* Wmg = (const float*)d_in[11]; const float* bmg = (const float*)d_in[12];
    const float* Wo1 = (const float*)d_in[13]; const float* bo1 = (const float*)d_in[14];
    const float* Wo2 = (const float*)d_in[15]; const float* bo2 = (const float*)d_in[16];
    const float* Wt1 = (const float*)d_in[17]; const float* bt1 = (const float*)d_in[18];
    const float* Wt2 = (const float*)d_in[19]; const float* bt2 = (const float*)d_in[20];
    const float* Wte = (const float*)d_in[21]; const float* bte = (const float*)d_in[22];
    const float* Wtg = (const float*)d_in[23]; const float* btg = (const float*)d_in[24];

    float* out = (float*)d_out;

    cudaFuncSetAttribute(main_kernel, cudaFuncAttributeMaxDynamicSharedMemorySize,
                         SMEM_BYTES);

    setup_kernel<<<dim3(128, 4), 128>>>(node, hidden, graph,
                                        Wm1, bm1, Wm2, bm2, bme, Wmg, bmg,
                                        Wo1, bo1, bo2,
                                        Wt1, bt1, Wt2, bt2, bte, Wtg, btg);

    main_kernel<<<BB * NN, 256, SMEM_BYTES>>>(edge, adj, Wme, Wte, Wo2, out);
}